// round 2
// baseline (speedup 1.0000x reference)
#include <cuda_runtime.h>
#include <math.h>

// Multilinear form tensor: z = sum_p T[p0,p1,p2,p3] * prod_i (1, cos xi, sin xi)[pi]
// Packed as float4 per (p0,p1,p2): (T[...,0], T[...,1], T[...,2], 0)
__device__ float4 g_T4[27];

// ---------------------------------------------------------------------------
// Precompute kernel: build U (entangler layers only), M = U^T Z0 U, then
// basis-change each pair index (a_i,b_i) -> (1, cos, sin) coefficients.
// One block, 128 threads, runs once per launch (~µs).
// ---------------------------------------------------------------------------
__global__ void precompute_T(const float* __restrict__ qw) {
    __shared__ float U[16][16];     // U[k][a]: column a = circuit applied to |a>
    __shared__ float Msh[16][16];
    __shared__ float bufA[256];
    __shared__ float bufB[256];
    __shared__ float qws[8];
    const int t = threadIdx.x;
    if (t < 8) qws[t] = qw[t];
    __syncthreads();

    if (t < 16) {
        float st[16];
#pragma unroll
        for (int k = 0; k < 16; k++) st[k] = (k == t) ? 1.f : 0.f;
#pragma unroll
        for (int l = 0; l < 2; l++) {
            // RY(qweights[l][w]) on each wire (wire i = bit 3-i)
#pragma unroll
            for (int w = 0; w < 4; w++) {
                float th = qws[l * 4 + w];
                float c, s;
                sincosf(0.5f * th, &s, &c);
                const int m = 1 << (3 - w);
#pragma unroll
                for (int k = 0; k < 16; k++) {
                    if (!(k & m)) {
                        float s0 = st[k], s1 = st[k | m];
                        st[k]     = c * s0 - s * s1;
                        st[k | m] = s * s0 + c * s1;
                    }
                }
            }
            // CNOT ring (0,1),(1,2),(2,3),(3,0): swap target within control=1 slab
            const int ctrl[4] = {0, 1, 2, 3};
            const int targ[4] = {1, 2, 3, 0};
#pragma unroll
            for (int e = 0; e < 4; e++) {
                const int mc = 1 << (3 - ctrl[e]);
                const int mt = 1 << (3 - targ[e]);
#pragma unroll
                for (int k = 0; k < 16; k++) {
                    if ((k & mc) && !(k & mt)) {
                        float tmp = st[k]; st[k] = st[k | mt]; st[k | mt] = tmp;
                    }
                }
            }
        }
#pragma unroll
        for (int k = 0; k < 16; k++) U[k][t] = st[k];
    }
    __syncthreads();

    // M[a][b] = sum_k sign(k) U[k][a] U[k][b], sign = +1 if wire0 bit (bit3)==0
    for (int e = t; e < 256; e += blockDim.x) {
        const int a = e >> 4, b = e & 15;
        float acc = 0.f;
#pragma unroll
        for (int k = 0; k < 16; k++) {
            float sgn = (k & 8) ? -1.f : 1.f;
            acc += sgn * U[k][a] * U[k][b];
        }
        Msh[a][b] = acc;
    }
    __syncthreads();

    // Gather pair-index tensor MP[j0,j1,j2,j3], j_i = a_i*2 + b_i
    for (int e = t; e < 256; e += blockDim.x) {
        const int j3 = e & 3, j2 = (e >> 2) & 3, j1 = (e >> 4) & 3, j0 = (e >> 6) & 3;
        const int a = (j0 >> 1) * 8 + (j1 >> 1) * 4 + (j2 >> 1) * 2 + (j3 >> 1);
        const int b = (j0 & 1) * 8 + (j1 & 1) * 4 + (j2 & 1) * 2 + (j3 & 1);
        bufA[e] = Msh[a][b];
    }
    __syncthreads();

    // Basis change per pair-index: out[0]=.5(x0+x3) [coef of 1], out[1]=.5(x0-x3)
    // [coef of cos], out[2]=.5(x1+x2) [coef of sin].
    // contract j0 (stride 64): bufB[p0*64 + r]
    for (int e = t; e < 192; e += blockDim.x) {
        const int p = e >> 6, r = e & 63;
        float x0 = bufA[r], x1 = bufA[64 + r], x2 = bufA[128 + r], x3 = bufA[192 + r];
        bufB[e] = (p == 0) ? 0.5f * (x0 + x3) : (p == 1) ? 0.5f * (x0 - x3) : 0.5f * (x1 + x2);
    }
    __syncthreads();
    // contract j1 (stride 16): bufA[(p0*3+p1)*16 + r]
    for (int e = t; e < 144; e += blockDim.x) {
        const int q = e >> 4, r = e & 15;
        const int p0 = q / 3, p1 = q % 3;
        const float* in = &bufB[p0 * 64 + r];
        float x0 = in[0], x1 = in[16], x2 = in[32], x3 = in[48];
        bufA[e] = (p1 == 0) ? 0.5f * (x0 + x3) : (p1 == 1) ? 0.5f * (x0 - x3) : 0.5f * (x1 + x2);
    }
    __syncthreads();
    // contract j2 (stride 4): bufB[(q*3+p2)*4 + j3]
    for (int e = t; e < 108; e += blockDim.x) {
        const int qq = e >> 2, j3 = e & 3;
        const int q = qq / 3, p2 = qq % 3;
        const float* in = &bufA[q * 16 + j3];
        float x0 = in[0], x1 = in[4], x2 = in[8], x3 = in[12];
        bufB[e] = (p2 == 0) ? 0.5f * (x0 + x3) : (p2 == 1) ? 0.5f * (x0 - x3) : 0.5f * (x1 + x2);
    }
    __syncthreads();
    // contract j3 (stride 1) and pack float4
    if (t < 27) {
        const float* in = &bufB[t * 4];
        float x0 = in[0], x1 = in[1], x2 = in[2], x3 = in[3];
        g_T4[t] = make_float4(0.5f * (x0 + x3), 0.5f * (x0 - x3), 0.5f * (x1 + x2), 0.f);
    }
}

// ---------------------------------------------------------------------------
// Main fused kernel: one CTA per image.
//   threads 0..195 : one 2x2 block each -> z via 80-FMA multilinear contraction
//   threads 0..239 : split-K (8 chunks x 30 outputs) for Linear(196,30)+ReLU
//   threads 0..1   : Linear(30,2)
// ---------------------------------------------------------------------------
__global__ __launch_bounds__(256) void hybrid_main(
    const float* __restrict__ x,
    const float* __restrict__ W1, const float* __restrict__ b1,
    const float* __restrict__ W2, const float* __restrict__ b2,
    float* __restrict__ out)
{
    __shared__ __align__(16) float img[784];
    __shared__ float4 sT[27];
    __shared__ float zbuf[196];
    __shared__ float part[240];
    __shared__ float hbuf[30];

    const int t = threadIdx.x;
    const int imgIdx = blockIdx.x;

    // Stage image: 196 coalesced float4 loads (784 floats = 3136B, 16B-aligned)
    if (t < 196) {
        const float4* x4 = (const float4*)x;
        ((float4*)img)[t] = x4[(size_t)imgIdx * 196 + t];
    }
    if (t >= 224 && t < 224 + 27) sT[t - 224] = g_T4[t - 224];
    __syncthreads();

    if (t < 196) {
        const int r = t / 14, c = t % 14;
        const float a0 = img[(2 * r) * 28 + 2 * c];
        const float a1 = img[(2 * r) * 28 + 2 * c + 1];
        const float a2 = img[(2 * r + 1) * 28 + 2 * c];
        const float a3 = img[(2 * r + 1) * 28 + 2 * c + 1];
        float c0, s0, c1, s1, c2, s2, c3, s3;
        __sincosf(a0, &s0, &c0);
        __sincosf(a1, &s1, &c1);
        __sincosf(a2, &s2, &c2);
        __sincosf(a3, &s3, &c3);

        // z = T contracted with (1,c,s) per wire; fuse wires 3 and 2
        float B9[9];
#pragma unroll
        for (int u = 0; u < 9; u++) {
            float4 t0 = sT[u * 3 + 0];
            float4 t1 = sT[u * 3 + 1];
            float4 t2 = sT[u * 3 + 2];
            float a = t0.x + t0.y * c3 + t0.z * s3;
            float b = t1.x + t1.y * c3 + t1.z * s3;
            float d = t2.x + t2.y * c3 + t2.z * s3;
            B9[u] = a + b * c2 + d * s2;
        }
        float C0 = B9[0] + B9[1] * c1 + B9[2] * s1;
        float C1 = B9[3] + B9[4] * c1 + B9[5] * s1;
        float C2 = B9[6] + B9[7] * c1 + B9[8] * s1;
        zbuf[t] = C0 + C1 * c0 + C2 * s0;
    }
    __syncthreads();

    // Linear(196,30): 8-way split-K over 240 threads
    if (t < 240) {
        const int j = t % 30, ch = t / 30;
        const int k0 = ch * 25;
        const int k1 = (k0 + 25 < 196) ? k0 + 25 : 196;
        float acc = 0.f;
        for (int k = k0; k < k1; k++)
            acc = fmaf(zbuf[k], __ldg(&W1[k * 30 + j]), acc);
        part[ch * 30 + j] = acc;
    }
    __syncthreads();

    if (t < 30) {
        float h = __ldg(&b1[t]);
#pragma unroll
        for (int c = 0; c < 8; c++) h += part[c * 30 + t];
        hbuf[t] = fmaxf(h, 0.f);
    }
    __syncthreads();

    if (t < 2) {
        float o = __ldg(&b2[t]);
#pragma unroll
        for (int i = 0; i < 30; i++)
            o = fmaf(hbuf[i], __ldg(&W2[i * 2 + t]), o);
        out[imgIdx * 2 + t] = o;
    }
}

extern "C" void kernel_launch(void* const* d_in, const int* in_sizes, int n_in,
                              void* d_out, int out_size) {
    const float* x  = (const float*)d_in[0];   // (4096, 784)
    const float* qw = (const float*)d_in[1];   // (2, 4)
    const float* W1 = (const float*)d_in[2];   // (196, 30)
    const float* b1 = (const float*)d_in[3];   // (30,)
    const float* W2 = (const float*)d_in[4];   // (30, 2)
    const float* b2 = (const float*)d_in[5];   // (2,)
    float* out = (float*)d_out;                // (4096, 2)

    const int B = in_sizes[0] / 784;

    precompute_T<<<1, 128>>>(qw);
    hybrid_main<<<B, 256>>>(x, W1, b1, W2, b2, out);
}